// round 16
// baseline (speedup 1.0000x reference)
#include <cuda_runtime.h>
#include <cuda_fp16.h>

// GaussianSoftmax: X[8,4096,16], sigma[1] -> softmax(exp(exp(-sqdist/sigma)), axis=2) [8,4096,4096]
//
// R16: ROW-PACKED f32x2 lanes. Pre-kernel writes g_xd[b][f][j] = (x_j[f], x_j[f])
// (duplicated, 4MB, L2-resident) and g_sqd[j] = (c*sq_j, c*sq_j). xq[f][rp] packs two
// ROWS -> 64 regs for all 8 rows (half of the f-pair layout that kept hitting the
// 255-reg cap in R11/R12/R14). acc lanes = rows, so the epilogue is fully packed:
// e2 = ffma2(acc, CM2d, sic2[rp] + sjd). Second exp via ex2.approx.f16x2 on the
// (colA,colB) half2 -> h is directly the stored half2 (MUFU 2 -> 1.5 ops/elem).
// With ~190 base regs the rotated schedule loads(k) -> epilogue(k-1) -> dot(k)
// finally fits. T=128, 8 rows x 2 cols/thread, barrier-free, 2 CTAs/SM.

#define BB 8
#define NN 4096
#define FF 16
#define RR 8
#define TT 128
#define NK 16                     // k-steps of 256 cols (2 per thread)
#define L2E  1.4426950408889634f
#define C528 0.5287663729448977f  // log2(log2(e))

typedef unsigned long long ull;

__device__ ull g_xd[BB * FF * NN];    // (x_j[f], x_j[f]) ; index b*65536 + f*4096 + j
__device__ ull g_sqd[BB * NN];        // (c*sq_j, c*sq_j) ; index b*4096 + j

// smem: hbuf uint[8][2048] = 64KB (uint m = cols 2m,2m+1), part, inv
#define HBUF_OFF 0
#define PART_OFF 65536
#define INV_OFF  (PART_OFF + 128)
#define SMEM_TOTAL (INV_OFF + 32)

__device__ __forceinline__ ull ffma2(ull a, ull b, ull c) {
    ull d; asm("fma.rn.f32x2 %0, %1, %2, %3;" : "=l"(d) : "l"(a), "l"(b), "l"(c)); return d;
}
__device__ __forceinline__ ull fadd2(ull a, ull b) {
    ull d; asm("add.rn.f32x2 %0, %1, %2;" : "=l"(d) : "l"(a), "l"(b)); return d;
}
__device__ __forceinline__ ull pk(float a, float b) {
    ull d; asm("mov.b64 %0, {%1, %2};" : "=l"(d) : "f"(a), "f"(b)); return d;
}
__device__ __forceinline__ float2 upk(ull v) {
    float2 r; asm("mov.b64 {%0, %1}, %2;" : "=f"(r.x), "=f"(r.y) : "l"(v)); return r;
}
__device__ __forceinline__ float ex2f(float x) {
    float r; asm("ex2.approx.f32 %0, %1;" : "=f"(r) : "f"(x)); return r;
}
__device__ __forceinline__ unsigned ex2h2(unsigned x) {
    unsigned r; asm("ex2.approx.f16x2 %0, %1;" : "=r"(r) : "r"(x)); return r;
}
__device__ __forceinline__ unsigned pkh2(float a, float b) {
    __half2 h = __floats2half2_rn(a, b);
    return *reinterpret_cast<unsigned*>(&h);
}
__device__ __forceinline__ void stcs4(float* p, float4 v) {
    asm volatile("st.global.cs.v4.f32 [%0], {%1, %2, %3, %4};"
                 :: "l"(p), "f"(v.x), "f"(v.y), "f"(v.z), "f"(v.w) : "memory");
}
__device__ __forceinline__ ulonglong2 ldg_nc128(const ulonglong2* p) {
    ulonglong2 v;
    asm("ld.global.nc.v2.b64 {%0, %1}, [%2];" : "=l"(v.x), "=l"(v.y) : "l"(p));
    return v;
}

// ---- pre-kernel: duplicated transposed X + duplicated cexp*||x_j||^2 ----
__global__ void __launch_bounds__(256)
prep_kernel(const float* __restrict__ X, const float* __restrict__ sigma) {
    int idx = blockIdx.x * 256 + threadIdx.x;          // b*4096 + j
    int b = idx >> 12, j = idx & 4095;
    const float4* p = reinterpret_cast<const float4*>(X) + (size_t)idx * 4;
    ull* xd = g_xd + (size_t)b * 65536 + j;            // + f*4096
    float s = 0.f;
    #pragma unroll
    for (int q = 0; q < 4; ++q) {
        float4 v = p[q];
        s += v.x * v.x + v.y * v.y + v.z * v.z + v.w * v.w;
        xd[(4 * q + 0) * 4096] = pk(v.x, v.x);
        xd[(4 * q + 1) * 4096] = pk(v.y, v.y);
        xd[(4 * q + 2) * 4096] = pk(v.z, v.z);
        xd[(4 * q + 3) * 4096] = pk(v.w, v.w);
    }
    float sjc = (-L2E / sigma[0]) * s;
    g_sqd[idx] = pk(sjc, sjc);
}

__global__ void __launch_bounds__(TT, 2)
GaussianSoftmax_67714454389333_kernel(const float* __restrict__ X,
                                      const float* __restrict__ sigma,
                                      float* __restrict__ out) {
    extern __shared__ char smem_raw[];
    unsigned* hbuf = reinterpret_cast<unsigned*>(smem_raw + HBUF_OFF);  // [8][2048]

    const int tid = threadIdx.x;
    const int b = blockIdx.y;
    const int i0 = blockIdx.x * RR;

    const float* Xb = X + (size_t)b * NN * FF;

    const float sg = sigma[0];
    const float cexp = -L2E / sg;
    const float CM2s = -2.0f * cexp;
    const ull CM2d = pk(CM2s, CM2s);

    // ---- xq: ROW-packed xi in regs (16 f x 4 row-pairs = 64 regs) + sic2 ----
    ull xq[FF][4];
    ull sic2[4];
    #pragma unroll
    for (int rp = 0; rp < 4; ++rp) {
        float se = 0.f, so = 0.f;
        #pragma unroll
        for (int f = 0; f < FF; ++f) {
            float ve = Xb[(size_t)(i0 + 2 * rp) * FF + f];
            float vo = Xb[(size_t)(i0 + 2 * rp + 1) * FF + f];
            se = fmaf(ve, ve, se);
            so = fmaf(vo, vo, so);
            xq[f][rp] = pk(ve, vo);
        }
        sic2[rp] = pk(fmaf(cexp, se, C528), fmaf(cexp, so, C528));
    }

    // g_xd viewed as ulonglong2[f][2048] per batch: LDG.128 = colpair x 1 f
    const ulonglong2* xd2 =
        reinterpret_cast<const ulonglong2*>(g_xd) + (size_t)b * 32768;
    const ulonglong2* sqd2 =
        reinterpret_cast<const ulonglong2*>(g_sqd) + (size_t)b * 2048;

    float rsum[RR];
    #pragma unroll
    for (int r = 0; r < RR; ++r) rsum[r] = 0.f;

    // ---- prologue: loads(0) + dot(0) ----
    ulonglong2 buf[FF];
    #pragma unroll
    for (int f = 0; f < FF; ++f)
        buf[f] = ldg_nc128(xd2 + f * 2048 + tid);
    ulonglong2 sjd = ldg_nc128(sqd2 + tid);

    ull accA[4], accB[4];
    #pragma unroll
    for (int rp = 0; rp < 4; ++rp) { accA[rp] = 0; accB[rp] = 0; }
    #pragma unroll
    for (int f = 0; f < FF; ++f) {
        ulonglong2 xj = buf[f];
        #pragma unroll
        for (int rp = 0; rp < 4; ++rp) {
            accA[rp] = ffma2(xj.x, xq[f][rp], accA[rp]);
            accB[rp] = ffma2(xj.y, xq[f][rp], accB[rp]);
        }
    }
    ulonglong2 sjdP = sjd;

    // ---- rotated mainloop: loads(k) -> epilogue(k-1) -> dot(k) ----
    #pragma unroll 1
    for (int k = 1; k < NK; ++k) {
        const int m = k * 128 + tid;

        // issue loads for step k (land while the epilogue below runs)
        #pragma unroll
        for (int f = 0; f < FF; ++f)
            buf[f] = ldg_nc128(xd2 + f * 2048 + m);
        sjd = ldg_nc128(sqd2 + m);

        // epilogue for step k-1 (packed rows; second exp in f16x2)
        const int mp = m - 128;
        #pragma unroll
        for (int rp = 0; rp < 4; ++rp) {
            ull eA2 = ffma2(accA[rp], CM2d, fadd2(sic2[rp], sjdP.x));
            ull eB2 = ffma2(accB[rp], CM2d, fadd2(sic2[rp], sjdP.y));
            float2 eA = upk(eA2), eB = upk(eB2);
            float gAe = ex2f(eA.x), gAo = ex2f(eA.y);
            float gBe = ex2f(eB.x), gBo = ex2f(eB.y);
            unsigned hEv = ex2h2(pkh2(gAe, gBe));   // row 2rp,   cols (2mp,2mp+1)
            unsigned hOd = ex2h2(pkh2(gAo, gBo));   // row 2rp+1
            hbuf[(2 * rp) * 2048 + mp] = hEv;
            hbuf[(2 * rp + 1) * 2048 + mp] = hOd;
            float2 fe = __half22float2(*reinterpret_cast<__half2*>(&hEv));
            float2 fo = __half22float2(*reinterpret_cast<__half2*>(&hOd));
            rsum[2 * rp] += fe.x + fe.y;
            rsum[2 * rp + 1] += fo.x + fo.y;
            accA[rp] = 0; accB[rp] = 0;
        }

        // dot for step k
        #pragma unroll
        for (int f = 0; f < FF; ++f) {
            ulonglong2 xj = buf[f];
            #pragma unroll
            for (int rp = 0; rp < 4; ++rp) {
                accA[rp] = ffma2(xj.x, xq[f][rp], accA[rp]);
                accB[rp] = ffma2(xj.y, xq[f][rp], accB[rp]);
            }
        }
        sjdP = sjd;
    }

    // ---- tail epilogue (step NK-1) ----
    {
        const int mp = (NK - 1) * 128 + tid;
        #pragma unroll
        for (int rp = 0; rp < 4; ++rp) {
            ull eA2 = ffma2(accA[rp], CM2d, fadd2(sic2[rp], sjdP.x));
            ull eB2 = ffma2(accB[rp], CM2d, fadd2(sic2[rp], sjdP.y));
            float2 eA = upk(eA2), eB = upk(eB2);
            float gAe = ex2f(eA.x), gAo = ex2f(eA.y);
            float gBe = ex2f(eB.x), gBo = ex2f(eB.y);
            unsigned hEv = ex2h2(pkh2(gAe, gBe));
            unsigned hOd = ex2h2(pkh2(gAo, gBo));
            hbuf[(2 * rp) * 2048 + mp] = hEv;
            hbuf[(2 * rp + 1) * 2048 + mp] = hOd;
            float2 fe = __half22float2(*reinterpret_cast<__half2*>(&hEv));
            float2 fo = __half22float2(*reinterpret_cast<__half2*>(&hOd));
            rsum[2 * rp] += fe.x + fe.y;
            rsum[2 * rp + 1] += fo.x + fo.y;
        }
    }

    // ---- row-sum reduction (4 warps) ----
    float* part = reinterpret_cast<float*>(smem_raw + PART_OFF);   // [4][8]
    #pragma unroll
    for (int r = 0; r < RR; ++r) {
        float v = rsum[r];
        v += __shfl_xor_sync(0xffffffffu, v, 16);
        v += __shfl_xor_sync(0xffffffffu, v, 8);
        v += __shfl_xor_sync(0xffffffffu, v, 4);
        v += __shfl_xor_sync(0xffffffffu, v, 2);
        v += __shfl_xor_sync(0xffffffffu, v, 1);
        if ((tid & 31) == 0) part[(tid >> 5) * 8 + r] = v;
    }
    __syncthreads();
    float* invp = reinterpret_cast<float*>(smem_raw + INV_OFF);
    if (tid < RR) {
        float s = part[0 * 8 + tid] + part[1 * 8 + tid] +
                  part[2 * 8 + tid] + part[3 * 8 + tid];
        invp[tid] = 1.0f / s;
    }
    __syncthreads();

    // ---- phase 2: normalize fp16 h -> two STG.128 per uint4 (8 contig cols) ----
    float* outB = out + ((size_t)b * NN + i0) * NN;
    const uint4* h4 = reinterpret_cast<const uint4*>(hbuf);        // [8][512]
    #pragma unroll 4
    for (int it = 0; it < 32; ++it) {
        int c4 = it * TT + tid;          // 0..4095
        int r = c4 >> 9;
        int w = c4 & 511;                // 8-col group within row
        float inv = invp[r];
        uint4 v = h4[c4];
        float2 p0 = __half22float2(*reinterpret_cast<__half2*>(&v.x));
        float2 p1 = __half22float2(*reinterpret_cast<__half2*>(&v.y));
        float2 p2 = __half22float2(*reinterpret_cast<__half2*>(&v.z));
        float2 p3 = __half22float2(*reinterpret_cast<__half2*>(&v.w));
        float4 oA = make_float4(p0.x * inv, p0.y * inv, p1.x * inv, p1.y * inv);
        float4 oB = make_float4(p2.x * inv, p2.y * inv, p3.x * inv, p3.y * inv);
        float* po = outB + (size_t)r * NN + w * 8;
        stcs4(po, oA);
        stcs4(po + 4, oB);
    }
}

extern "C" void kernel_launch(void* const* d_in, const int* in_sizes, int n_in,
                              void* d_out, int out_size) {
    const float* X = (const float*)d_in[0];
    const float* sigma = (const float*)d_in[1];
    float* out = (float*)d_out;

    prep_kernel<<<BB * NN / 256, 256>>>(X, sigma);

    cudaFuncSetAttribute(GaussianSoftmax_67714454389333_kernel,
                         cudaFuncAttributeMaxDynamicSharedMemorySize, SMEM_TOTAL);
    dim3 grid(NN / RR, BB);   // (512, 8)
    GaussianSoftmax_67714454389333_kernel<<<grid, TT, SMEM_TOTAL>>>(X, sigma, out);
}

// round 17
// speedup vs baseline: 1.2966x; 1.2966x over previous
#include <cuda_runtime.h>
#include <cuda_fp16.h>

// GaussianSoftmax: X[8,4096,16], sigma[1] -> softmax(exp(exp(-sqdist/sigma)), axis=2) [8,4096,4096]
//
// R17: 3 CTAs/SM. xq is CTA-uniform, so only f-pairs 0..1 stay in registers (32 regs);
// f-pairs 2..7 live in a 384B smem table read via broadcast LDS.128 inside the dot
// loop. This cuts ~96 regs vs R10 (204 -> ~150), fitting the 168-reg cap of
// __launch_bounds__(128,3): 12 warps/SM in three independent barrier/phase domains.
// Mainloop otherwise identical to the proven R10 shape: barrier-free, 8 rows x 2
// contiguous cols/thread, 8x LDG.128 from L2-resident pre-transposed g_xt,
// h fp16 in smem (64KB), fp32 row sums, streaming STG.128 out.

#define BB 8
#define NN 4096
#define FF 16
#define RR 8
#define TT 128
#define NK 16                     // k-steps of 256 cols (2 per thread)
#define L2E  1.4426950408889634f
#define C528 0.5287663729448977f  // log2(log2(e))

typedef unsigned long long ull;

__device__ float g_sqc[BB * NN];      // cexp * ||x_j||^2
__device__ float g_xt[BB * FF * NN];  // [b][fp][j] float2

// smem: hbuf uint[8][2048] = 64KB, xqh ull[6][8] = 384B, part, inv
#define HBUF_OFF 0
#define XQH_OFF  65536                 // 16B-aligned
#define PART_OFF (XQH_OFF + 384)
#define INV_OFF  (PART_OFF + 128)
#define SMEM_TOTAL (INV_OFF + 32)      // 66080 B -> 3 CTAs/SM (198KB of 228KB)

__device__ __forceinline__ ull ffma2(ull a, ull b, ull c) {
    ull d; asm("fma.rn.f32x2 %0, %1, %2, %3;" : "=l"(d) : "l"(a), "l"(b), "l"(c)); return d;
}
__device__ __forceinline__ ull pk(float a, float b) {
    ull d; asm("mov.b64 %0, {%1, %2};" : "=l"(d) : "f"(a), "f"(b)); return d;
}
__device__ __forceinline__ float2 upk(ull v) {
    float2 r; asm("mov.b64 {%0, %1}, %2;" : "=f"(r.x), "=f"(r.y) : "l"(v)); return r;
}
__device__ __forceinline__ float ex2f(float x) {
    float r; asm("ex2.approx.f32 %0, %1;" : "=f"(r) : "f"(x)); return r;
}
__device__ __forceinline__ unsigned pkh2(float a, float b) {
    __half2 h = __floats2half2_rn(a, b);
    return *reinterpret_cast<unsigned*>(&h);
}
__device__ __forceinline__ void stcs4(float* p, float4 v) {
    asm volatile("st.global.cs.v4.f32 [%0], {%1, %2, %3, %4};"
                 :: "l"(p), "f"(v.x), "f"(v.y), "f"(v.z), "f"(v.w) : "memory");
}
__device__ __forceinline__ ulonglong2 ldg_nc128(const ulonglong2* p) {
    ulonglong2 v;
    asm("ld.global.nc.v2.b64 {%0, %1}, [%2];" : "=l"(v.x), "=l"(v.y) : "l"(p));
    return v;
}

// ---- pre-kernel: transpose X into f-pair rows + cexp*||x_j||^2 ----
__global__ void __launch_bounds__(256)
prep_kernel(const float* __restrict__ X, const float* __restrict__ sigma) {
    int idx = blockIdx.x * 256 + threadIdx.x;          // b*4096 + j
    int b = idx >> 12, j = idx & 4095;
    const float4* p = reinterpret_cast<const float4*>(X) + (size_t)idx * 4;
    float s = 0.f;
    float2* xtb = reinterpret_cast<float2*>(&g_xt[b * 65536]) + j;
    #pragma unroll
    for (int q = 0; q < 4; ++q) {
        float4 v = p[q];
        s += v.x * v.x + v.y * v.y + v.z * v.z + v.w * v.w;
        xtb[(2 * q + 0) * 4096] = make_float2(v.x, v.y);
        xtb[(2 * q + 1) * 4096] = make_float2(v.z, v.w);
    }
    g_sqc[idx] = (-L2E / sigma[0]) * s;
}

__global__ void __launch_bounds__(TT, 3)
GaussianSoftmax_67714454389333_kernel(const float* __restrict__ X,
                                      const float* __restrict__ sigma,
                                      float* __restrict__ out) {
    extern __shared__ char smem_raw[];
    unsigned* hbuf = reinterpret_cast<unsigned*>(smem_raw + HBUF_OFF);  // [8][2048]
    const ulonglong2* xqh2 = reinterpret_cast<const ulonglong2*>(smem_raw + XQH_OFF); // [6][4]

    const int tid = threadIdx.x;
    const int b = blockIdx.y;
    const int i0 = blockIdx.x * RR;

    const float* Xb = X + (size_t)b * NN * FF;

    const float sg = sigma[0];
    const float cexp = -L2E / sg;
    const float CM2s = -2.0f * cexp;

    // ---- phase 0: xqh table (f-pairs 2..7, CTA-uniform) written by 48 threads ----
    if (tid < 48) {
        int fpi = tid >> 3, r = tid & 7;           // fp = 2 + fpi
        const float* row = Xb + (size_t)(i0 + r) * FF + (2 + fpi) * 2;
        reinterpret_cast<ull*>(smem_raw + XQH_OFF)[fpi * 8 + r] = pk(row[0], row[1]);
    }

    // ---- xqlo: f-pairs 0..1 in regs (32) + sic (per-thread, from cached LDG) ----
    ull xqlo[2][RR];
    float sic[RR];
    #pragma unroll
    for (int r = 0; r < RR; ++r) {
        const float* row = Xb + (size_t)(i0 + r) * FF;
        float s = 0.f;
        #pragma unroll
        for (int f = 0; f < FF; ++f) { float v = row[f]; s = fmaf(v, v, s); }
        sic[r] = fmaf(cexp, s, C528);
        xqlo[0][r] = pk(row[0], row[1]);
        xqlo[1][r] = pk(row[2], row[3]);
    }
    __syncthreads();   // xqh visible

    // xt viewed as ulonglong2[fp][2048] per batch: one LDG.128 = 2 cols x 1 f-pair
    const ulonglong2* xt2 =
        reinterpret_cast<const ulonglong2*>(g_xt) + (size_t)b * 16384;
    const float2* sq2 = reinterpret_cast<const float2*>(g_sqc) + b * 2048;

    float rsum[RR];
    #pragma unroll
    for (int r = 0; r < RR; ++r) rsum[r] = 0.f;

    // ---- barrier-free mainloop: 16 steps x (8 rows x 2 contiguous cols) ----
    #pragma unroll 1
    for (int k = 0; k < NK; ++k) {
        const int m = k * 128 + tid;     // col-pair index (cols 2m, 2m+1)

        // loads for this step (L2-resident; 12 warps/SM hide latency)
        ulonglong2 buf[8];
        #pragma unroll
        for (int fp = 0; fp < 8; ++fp)
            buf[fp] = ldg_nc128(xt2 + fp * 2048 + m);
        float2 sj = __ldg(sq2 + m);

        // dot products: f-pairs 0..1 from regs, 2..7 from smem broadcast
        ull accA[RR], accB[RR];
        #pragma unroll
        for (int r = 0; r < RR; ++r) { accA[r] = 0; accB[r] = 0; }
        #pragma unroll
        for (int fp = 0; fp < 2; ++fp) {
            ulonglong2 xj = buf[fp];
            #pragma unroll
            for (int r = 0; r < RR; ++r) {
                accA[r] = ffma2(xj.x, xqlo[fp][r], accA[r]);
                accB[r] = ffma2(xj.y, xqlo[fp][r], accB[r]);
            }
        }
        #pragma unroll
        for (int fp = 2; fp < 8; ++fp) {
            ulonglong2 xj = buf[fp];
            #pragma unroll
            for (int rq = 0; rq < 4; ++rq) {
                ulonglong2 q = xqh2[(fp - 2) * 4 + rq];   // rows 2rq, 2rq+1 (broadcast)
                accA[2 * rq + 0] = ffma2(xj.x, q.x, accA[2 * rq + 0]);
                accB[2 * rq + 0] = ffma2(xj.y, q.x, accB[2 * rq + 0]);
                accA[2 * rq + 1] = ffma2(xj.x, q.y, accA[2 * rq + 1]);
                accB[2 * rq + 1] = ffma2(xj.y, q.y, accB[2 * rq + 1]);
            }
        }

        // epilogue: e = CM2s*dot + (sic[r]+sj) ; h = 2^(2^e) ; fp16 h to smem
        #pragma unroll
        for (int r = 0; r < RR; ++r) {
            float base = sic[r];
            float2 aA = upk(accA[r]);
            float2 aB = upk(accB[r]);
            float eA = fmaf(CM2s, aA.x + aA.y, base + sj.x);
            float eB = fmaf(CM2s, aB.x + aB.y, base + sj.y);
            float hA = ex2f(ex2f(eA));
            float hB = ex2f(ex2f(eB));
            rsum[r] += hA + hB;
            hbuf[r * 2048 + m] = pkh2(hA, hB);   // cols 2m, 2m+1
        }
    }

    // ---- row-sum reduction (4 warps) ----
    float* part = reinterpret_cast<float*>(smem_raw + PART_OFF);   // [4][8]
    #pragma unroll
    for (int r = 0; r < RR; ++r) {
        float v = rsum[r];
        v += __shfl_xor_sync(0xffffffffu, v, 16);
        v += __shfl_xor_sync(0xffffffffu, v, 8);
        v += __shfl_xor_sync(0xffffffffu, v, 4);
        v += __shfl_xor_sync(0xffffffffu, v, 2);
        v += __shfl_xor_sync(0xffffffffu, v, 1);
        if ((tid & 31) == 0) part[(tid >> 5) * 8 + r] = v;
    }
    __syncthreads();
    float* invp = reinterpret_cast<float*>(smem_raw + INV_OFF);
    if (tid < RR) {
        float s = part[0 * 8 + tid] + part[1 * 8 + tid] +
                  part[2 * 8 + tid] + part[3 * 8 + tid];
        invp[tid] = 1.0f / s;
    }
    __syncthreads();

    // ---- phase 2: normalize fp16 h -> two STG.128 per uint4 (8 contig cols) ----
    float* outB = out + ((size_t)b * NN + i0) * NN;
    const uint4* h4 = reinterpret_cast<const uint4*>(hbuf);        // [8][512]
    #pragma unroll 4
    for (int it = 0; it < 32; ++it) {
        int c4 = it * TT + tid;          // 0..4095
        int r = c4 >> 9;
        int w = c4 & 511;                // 8-col group within row
        float inv = invp[r];
        uint4 v = h4[c4];
        float2 p0 = __half22float2(*reinterpret_cast<__half2*>(&v.x));
        float2 p1 = __half22float2(*reinterpret_cast<__half2*>(&v.y));
        float2 p2 = __half22float2(*reinterpret_cast<__half2*>(&v.z));
        float2 p3 = __half22float2(*reinterpret_cast<__half2*>(&v.w));
        float4 oA = make_float4(p0.x * inv, p0.y * inv, p1.x * inv, p1.y * inv);
        float4 oB = make_float4(p2.x * inv, p2.y * inv, p3.x * inv, p3.y * inv);
        float* po = outB + (size_t)r * NN + w * 8;
        stcs4(po, oA);
        stcs4(po + 4, oB);
    }
}

extern "C" void kernel_launch(void* const* d_in, const int* in_sizes, int n_in,
                              void* d_out, int out_size) {
    const float* X = (const float*)d_in[0];
    const float* sigma = (const float*)d_in[1];
    float* out = (float*)d_out;

    prep_kernel<<<BB * NN / 256, 256>>>(X, sigma);

    cudaFuncSetAttribute(GaussianSoftmax_67714454389333_kernel,
                         cudaFuncAttributeMaxDynamicSharedMemorySize, SMEM_TOTAL);
    dim3 grid(NN / RR, BB);   // (512, 8)
    GaussianSoftmax_67714454389333_kernel<<<grid, TT, SMEM_TOTAL>>>(X, sigma, out);
}